// round 2
// baseline (speedup 1.0000x reference)
#include <cuda_runtime.h>
#include <math.h>
#include <stdint.h>

#define NSAMP  8
#define NEXP   256
#define NMARK  10
#define KBOUND 40

// cos with explicit Cody-Waite reduction by 2*pi (t up to ~350), then MUFU cos.
// Angle error ~2.5e-7 — needed because accept is a hard threshold.
__device__ __forceinline__ float cos_cw(float t) {
    const float INV2PI   = 0.15915494309189535f;
    const float TWOPI_HI = 6.2831854820251465f;   // float(2*pi)
    const float TWOPI_LO = -1.7484555e-07f;       // 2*pi - TWOPI_HI
    float k = rintf(t * INV2PI);
    float r = fmaf(-k, TWOPI_HI, t);
    r = fmaf(-k, TWOPI_LO, r);
    return __cosf(r);
}

// sum_m softplus(sc[m]*c + c0[m]) with a SINGLE log:
//   softplus(x) = max(x,0) + log(1 + exp(-|x|))
//   sum = sum_m max(x_m,0) + log( prod_m (1 + exp(-|x_m|)) )
// prod in (1, 2^10]; one LG2 instead of ten. 10 EX2 + 1 LG2 total.
__device__ __forceinline__ float total_intensity(float c,
                                                 const float* __restrict__ c0,
                                                 const float* __restrict__ sc) {
    float lin = 0.0f, prod = 1.0f;
#pragma unroll
    for (int m = 0; m < NMARK; m++) {
        float x = fmaf(sc[m], c, c0[m]);
        lin += fmaxf(x, 0.0f);
        prod *= (1.0f + __expf(-fabsf(x)));
    }
    return lin + __logf(prod);
}

__global__ void __launch_bounds__(256) sampler_kernel(
    const float* __restrict__ time_seq,
    const float* __restrict__ dt_seq,
    const int*   __restrict__ ev_w,     // raw 32-bit words of event_seq (int32 or int64)
    const float* __restrict__ exp_raw,
    const float* __restrict__ unif,
    const float* __restrict__ emb,
    const float* __restrict__ scale,
    const float* __restrict__ bias,
    float* __restrict__ out_res,
    float* __restrict__ out_w,
    int write_w)
{
    const int row  = blockIdx.x;
    const int tid  = threadIdx.x;
    const int lane = tid & 31;
    const int warp = tid >> 5;

    __shared__ float    s_c0[NMARK];
    __shared__ float    s_sc[NMARK];
    __shared__ unsigned s_red[8 * NSAMP];   // also reused for boundary max (first 8)
    __shared__ float    s_upper;

    // ---- issue the big global loads immediately (overlap with boundary phase) ----
    const float exr = exp_raw[(size_t)row * NEXP + tid];
    const float* uptr = unif + (size_t)row * (NSAMP * NEXP) + tid;
    float u[NSAMP];
#pragma unroll
    for (int j = 0; j < NSAMP; j++) u[j] = uptr[(size_t)j * NEXP];

    const float t0  = time_seq[row];
    const float dtv = dt_seq[row];

    if (tid < NMARK) {
        // int64 vs int32 detection: for LE int64 with values in [0,20), all odd
        // 32-bit words are 0. Check 20 odd words via one ballot over 10 lanes.
        int a = ev_w[2 * tid + 1] | ev_w[2 * (tid + NMARK) + 1];
        unsigned ball = __ballot_sync(0x3FFu, a != 0);
        int ev = (ball == 0u) ? ev_w[2 * row] : ev_w[row];
        s_c0[tid] = emb[ev * NMARK + tid] + bias[tid];
        s_sc[tid] = scale[tid];
    }
    __syncthreads();

    float c0r[NMARK], scr[NMARK];
#pragma unroll
    for (int m = 0; m < NMARK; m++) { c0r[m] = s_c0[m]; scr[m] = s_sc[m]; }

    // ---- intensity upper bound: max over 40 boundary samples (lam >= 0) ----
    float lam = 0.0f;
    if (tid < KBOUND) {
        float t = fmaf(dtv, (float)tid * (1.0f / 39.0f), t0);
        lam = total_intensity(cos_cw(t), c0r, scr);
    }
    unsigned lmax = __reduce_max_sync(0xffffffffu, __float_as_uint(lam));
    if (lane == 0) s_red[warp] = lmax;
    __syncthreads();
    if (tid == 0) {
        unsigned m = s_red[0];
#pragma unroll
        for (int w2 = 1; w2 < 8; w2++) m = (s_red[w2] > m) ? s_red[w2] : m;
        s_upper = 1.5f * __uint_as_float(m);   // OVER_SAMPLE_RATE
    }
    __syncthreads();
    const float upper = s_upper;

    // ---- per-candidate total intensity + accept test ----
    const float ex = __fdividef(exr, upper);          // exp_numbers (>= 0)
    const float total = total_intensity(cos_cw(t0 + ex), c0r, scr);

    // accept if u*upper < total; candidate value is ex (same for all j).
    // ex >= 0 so float bits are order-monotone as u32; INF = 0x7F800000.
    const unsigned exbits = __float_as_uint(ex);
#pragma unroll
    for (int j = 0; j < NSAMP; j++) {
        unsigned cand = (u[j] * upper < total) ? exbits : 0x7F800000u;
        unsigned wmin = __reduce_min_sync(0xffffffffu, cand);
        if (lane == 0) s_red[warp * NSAMP + j] = wmin;
    }
    __syncthreads();

    if (tid < NSAMP) {
        unsigned m = s_red[tid];
#pragma unroll
        for (int w2 = 1; w2 < 8; w2++) {
            unsigned v = s_red[w2 * NSAMP + tid];
            m = (v < m) ? v : m;
        }
        float r = (m >= 0x7F800000u) ? 5.0f : __uint_as_float(m);  // DTIME_MAX
        r = fminf(r, 1e5f);
        out_res[row * NSAMP + tid] = r;
        if (write_w) out_w[row * NSAMP + tid] = 0.125f;  // 1/NUM_SAMPLES
    }
}

extern "C" void kernel_launch(void* const* d_in, const int* in_sizes, int n_in,
                              void* d_out, int out_size) {
    const float* time_seq = (const float*)d_in[0];
    const float* dt_seq   = (const float*)d_in[1];
    const int*   ev_w     = (const int*)  d_in[2];
    const float* exp_raw  = (const float*)d_in[3];
    const float* unif     = (const float*)d_in[4];
    const float* emb      = (const float*)d_in[5];
    const float* scale    = (const float*)d_in[6];
    const float* bias     = (const float*)d_in[7];

    const int n_rows    = in_sizes[0];          // B*S = 16384
    const int res_elems = n_rows * NSAMP;
    float* res  = (float*)d_out;
    float* wout = res + res_elems;
    const int write_w = (out_size >= 2 * res_elems) ? 1 : 0;

    sampler_kernel<<<n_rows, 256>>>(time_seq, dt_seq, ev_w, exp_raw, unif,
                                    emb, scale, bias, res, wout, write_w);
}

// round 3
// speedup vs baseline: 1.3986x; 1.3986x over previous
#include <cuda_runtime.h>
#include <math.h>
#include <stdint.h>

#define NSAMP  8
#define NEXP   256
#define NMARK  10
#define KBOUND 40

// cos with explicit Cody-Waite reduction by 2*pi (t up to ~350), then MUFU cos.
// Angle error ~2.5e-7 — needed because accept is a hard threshold.
__device__ __forceinline__ float cos_cw(float t) {
    const float INV2PI   = 0.15915494309189535f;
    const float TWOPI_HI = 6.2831854820251465f;   // float(2*pi)
    const float TWOPI_LO = -1.7484555e-07f;       // 2*pi - TWOPI_HI
    float k = rintf(t * INV2PI);
    float r = fmaf(-k, TWOPI_HI, t);
    r = fmaf(-k, TWOPI_LO, r);
    return __cosf(r);
}

// sum_m softplus(sc[m]*c + c0[m]) with a SINGLE log:
//   sum = sum_m max(x_m,0) + log( prod_m (1 + exp(-|x_m|)) ),  prod in (1, 2^10]
// 10 EX2 + 1 LG2 instead of 10 EX2 + 10 LG2.
__device__ __forceinline__ float total_intensity(float c,
                                                 const float* __restrict__ c0,
                                                 const float* __restrict__ sc) {
    float lin = 0.0f, prod = 1.0f;
#pragma unroll
    for (int m = 0; m < NMARK; m++) {
        float x = fmaf(sc[m], c, c0[m]);
        lin += fmaxf(x, 0.0f);
        prod *= (1.0f + __expf(-fabsf(x)));
    }
    return lin + __logf(prod);
}

__global__ void __launch_bounds__(256) sampler_kernel(
    const float* __restrict__ time_seq,
    const float* __restrict__ dt_seq,
    const int*   __restrict__ ev_w,     // raw 32-bit words of event_seq (int32 or int64)
    const float* __restrict__ exp_raw,
    const float* __restrict__ unif,
    const float* __restrict__ emb,
    const float* __restrict__ scale,
    const float* __restrict__ bias,
    float* __restrict__ out_res,
    float* __restrict__ out_w,
    int write_w)
{
    const int row  = blockIdx.x;
    const int tid  = threadIdx.x;
    const int lane = tid & 31;
    const int warp = tid >> 5;

    __shared__ float s_c0[NMARK];
    __shared__ float s_sc[NMARK];
    __shared__ float s_wmax[8];
    __shared__ float s_upper;
    __shared__ float s_ex[NEXP];
    __shared__ float s_tot[NEXP];

    // ---- issue the exp_raw load immediately ----
    const float exr = exp_raw[(size_t)row * NEXP + tid];
    const float t0  = time_seq[row];
    const float dtv = dt_seq[row];

    if (tid < NMARK) {
        // int64 vs int32 detection: for LE int64 with values in [0,20), all odd
        // 32-bit words are 0. Check 20 odd words via one ballot over 10 lanes.
        int a = ev_w[2 * tid + 1] | ev_w[2 * (tid + NMARK) + 1];
        unsigned ball = __ballot_sync(0x3FFu, a != 0);
        int ev = (ball == 0u) ? ev_w[2 * row] : ev_w[row];
        s_c0[tid] = emb[ev * NMARK + tid] + bias[tid];
        s_sc[tid] = scale[tid];
    }
    __syncthreads();

    float c0r[NMARK], scr[NMARK];
#pragma unroll
    for (int m = 0; m < NMARK; m++) { c0r[m] = s_c0[m]; scr[m] = s_sc[m]; }

    // ---- intensity upper bound: max over 40 boundary samples (lam >= 0) ----
    float lam = 0.0f;
    if (tid < KBOUND) {
        float t = fmaf(dtv, (float)tid * (1.0f / 39.0f), t0);
        lam = total_intensity(cos_cw(t), c0r, scr);
    }
#pragma unroll
    for (int o = 16; o; o >>= 1)
        lam = fmaxf(lam, __shfl_xor_sync(0xffffffffu, lam, o));
    if (lane == 0) s_wmax[warp] = lam;   // only warps 0,1 hold real data, rest are 0
    __syncthreads();
    if (tid == 0)
        s_upper = 1.5f * fmaxf(s_wmax[0], s_wmax[1]);   // OVER_SAMPLE_RATE
    __syncthreads();
    const float upper = s_upper;

    // ---- phase 1: per-candidate ex + total intensity -> smem ----
    const float ex = __fdividef(exr, upper);          // exp_numbers (>= 0)
    const float total = total_intensity(cos_cw(t0 + ex), c0r, scr);
    s_ex[tid]  = ex;
    s_tot[tid] = total;
    __syncthreads();

    // ---- phase 2: warp j owns sample slot j; scan all 256 candidates ----
    {
        const int j = warp;   // 8 warps == NSAMP slots
        const float* up = unif + (size_t)row * (NSAMP * NEXP) + (size_t)j * NEXP;
        float m = INFINITY;
#pragma unroll
        for (int i = 0; i < NEXP / 32; i++) {
            int e = lane + 32 * i;
            float uu = up[e];                       // coalesced 128B per iter
            if (uu * upper < s_tot[e])              // accept test (same as ref ordering)
                m = fminf(m, s_ex[e]);
        }
#pragma unroll
        for (int o = 16; o; o >>= 1)
            m = fminf(m, __shfl_xor_sync(0xffffffffu, m, o));
        if (lane == 0) {
            float r = isinf(m) ? 5.0f : m;          // DTIME_MAX when none accepted
            r = fminf(r, 1e5f);
            out_res[row * NSAMP + j] = r;
            if (write_w) out_w[row * NSAMP + j] = 0.125f;  // 1/NUM_SAMPLES
        }
    }
}

extern "C" void kernel_launch(void* const* d_in, const int* in_sizes, int n_in,
                              void* d_out, int out_size) {
    const float* time_seq = (const float*)d_in[0];
    const float* dt_seq   = (const float*)d_in[1];
    const int*   ev_w     = (const int*)  d_in[2];
    const float* exp_raw  = (const float*)d_in[3];
    const float* unif     = (const float*)d_in[4];
    const float* emb      = (const float*)d_in[5];
    const float* scale    = (const float*)d_in[6];
    const float* bias     = (const float*)d_in[7];

    const int n_rows    = in_sizes[0];          // B*S = 16384
    const int res_elems = n_rows * NSAMP;
    float* res  = (float*)d_out;
    float* wout = res + res_elems;
    const int write_w = (out_size >= 2 * res_elems) ? 1 : 0;

    sampler_kernel<<<n_rows, 256>>>(time_seq, dt_seq, ev_w, exp_raw, unif,
                                    emb, scale, bias, res, wout, write_w);
}

// round 4
// speedup vs baseline: 1.4691x; 1.0504x over previous
#include <cuda_runtime.h>
#include <math.h>
#include <stdint.h>

#define NSAMP  8
#define NEXP   256
#define NMARK  10
#define KBOUND 40

// cos with explicit Cody-Waite reduction by 2*pi (t up to ~350), then MUFU cos.
__device__ __forceinline__ float cos_cw(float t) {
    const float INV2PI   = 0.15915494309189535f;
    const float TWOPI_HI = 6.2831854820251465f;
    const float TWOPI_LO = -1.7484555e-07f;
    float k = rintf(t * INV2PI);
    float r = fmaf(-k, TWOPI_HI, t);
    r = fmaf(-k, TWOPI_LO, r);
    return __cosf(r);
}

// sum_m softplus(sc[m]*c + c0[m]) with a SINGLE log (10 EX2 + 1 LG2).
__device__ __forceinline__ float total_intensity(float c,
                                                 const float* __restrict__ c0,
                                                 const float* __restrict__ sc) {
    float lin = 0.0f, prod = 1.0f;
#pragma unroll
    for (int m = 0; m < NMARK; m++) {
        float x = fmaf(sc[m], c, c0[m]);
        lin += fmaxf(x, 0.0f);
        prod *= (1.0f + __expf(-fabsf(x)));
    }
    return lin + __logf(prod);
}

__device__ __forceinline__ void cp_async16(void* smem_dst, const void* gmem_src) {
    unsigned saddr = (unsigned)__cvta_generic_to_shared(smem_dst);
    asm volatile("cp.async.cg.shared.global [%0], [%1], 16;\n"
                 :: "r"(saddr), "l"(gmem_src) : "memory");
}

__global__ void __launch_bounds__(256) sampler_kernel(
    const float* __restrict__ time_seq,
    const float* __restrict__ dt_seq,
    const int*   __restrict__ ev_w,
    const float* __restrict__ exp_raw,
    const float* __restrict__ unif,
    const float* __restrict__ emb,
    const float* __restrict__ scale,
    const float* __restrict__ bias,
    float* __restrict__ out_res,
    float* __restrict__ out_w,
    int write_w)
{
    const int row  = blockIdx.x;
    const int tid  = threadIdx.x;
    const int lane = tid & 31;
    const int warp = tid >> 5;

    __shared__ __align__(16) float s_unif[NSAMP * NEXP];  // 8 KB
    __shared__ __align__(16) float s_ex[NEXP];
    __shared__ __align__(16) float s_tot[NEXP];
    __shared__ float s_c0[NMARK];
    __shared__ float s_sc[NMARK];
    __shared__ float s_wmax[8];
    __shared__ float s_upper;

    // ---- prefetch this block's unif slice (8 KB) via cp.async: overlaps
    //      the whole boundary + phase-1 compute with the DRAM stream ----
    {
        const float* urow = unif + (size_t)row * (NSAMP * NEXP) + 8 * tid;
        cp_async16(&s_unif[8 * tid],     urow);
        cp_async16(&s_unif[8 * tid + 4], urow + 4);
        asm volatile("cp.async.commit_group;\n" ::: "memory");
    }

    const float exr = exp_raw[(size_t)row * NEXP + tid];
    const float t0  = time_seq[row];
    const float dtv = dt_seq[row];

    if (tid < NMARK) {
        // int64 vs int32 detection (LE int64 with values < 20 => odd words all 0)
        int a = ev_w[2 * tid + 1] | ev_w[2 * (tid + NMARK) + 1];
        unsigned ball = __ballot_sync(0x3FFu, a != 0);
        int ev = (ball == 0u) ? ev_w[2 * row] : ev_w[row];
        s_c0[tid] = emb[ev * NMARK + tid] + bias[tid];
        s_sc[tid] = scale[tid];
    }
    __syncthreads();

    float c0r[NMARK], scr[NMARK];
#pragma unroll
    for (int m = 0; m < NMARK; m++) { c0r[m] = s_c0[m]; scr[m] = s_sc[m]; }

    // ---- intensity upper bound: max over 40 boundary samples ----
    float lam = 0.0f;
    if (tid < KBOUND) {
        float t = fmaf(dtv, (float)tid * (1.0f / 39.0f), t0);
        lam = total_intensity(cos_cw(t), c0r, scr);
    }
#pragma unroll
    for (int o = 16; o; o >>= 1)
        lam = fmaxf(lam, __shfl_xor_sync(0xffffffffu, lam, o));
    if (lane == 0) s_wmax[warp] = lam;
    __syncthreads();
    if (tid == 0)
        s_upper = 1.5f * fmaxf(s_wmax[0], s_wmax[1]);   // OVER_SAMPLE_RATE
    __syncthreads();
    const float upper = s_upper;

    // ---- phase 1: per-candidate ex + total intensity -> smem ----
    const float ex = __fdividef(exr, upper);
    const float total = total_intensity(cos_cw(t0 + ex), c0r, scr);
    s_ex[tid]  = ex;
    s_tot[tid] = total;

    asm volatile("cp.async.wait_group 0;\n" ::: "memory");
    __syncthreads();

    // ---- phase 2: warp j owns sample slot j; all LDS.128, conflict-free ----
    {
        const int j = warp;
        const float4* su = (const float4*)(s_unif + j * NEXP);
        const float4* pe = (const float4*)s_ex;
        const float4* pt = (const float4*)s_tot;
        float m = INFINITY;
#pragma unroll
        for (int half = 0; half < 2; half++) {
            int q = 32 * half + lane;          // float4 index: covers e = 4q..4q+3
            float4 u4 = su[q];
            float4 e4 = pe[q];
            float4 t4 = pt[q];
            if (u4.x * upper < t4.x) m = fminf(m, e4.x);
            if (u4.y * upper < t4.y) m = fminf(m, e4.y);
            if (u4.z * upper < t4.z) m = fminf(m, e4.z);
            if (u4.w * upper < t4.w) m = fminf(m, e4.w);
        }
#pragma unroll
        for (int o = 16; o; o >>= 1)
            m = fminf(m, __shfl_xor_sync(0xffffffffu, m, o));
        if (lane == 0) {
            float r = isinf(m) ? 5.0f : m;     // DTIME_MAX when none accepted
            r = fminf(r, 1e5f);
            out_res[row * NSAMP + j] = r;
            if (write_w) out_w[row * NSAMP + j] = 0.125f;
        }
    }
}

extern "C" void kernel_launch(void* const* d_in, const int* in_sizes, int n_in,
                              void* d_out, int out_size) {
    const float* time_seq = (const float*)d_in[0];
    const float* dt_seq   = (const float*)d_in[1];
    const int*   ev_w     = (const int*)  d_in[2];
    const float* exp_raw  = (const float*)d_in[3];
    const float* unif     = (const float*)d_in[4];
    const float* emb      = (const float*)d_in[5];
    const float* scale    = (const float*)d_in[6];
    const float* bias     = (const float*)d_in[7];

    const int n_rows    = in_sizes[0];          // B*S = 16384
    const int res_elems = n_rows * NSAMP;
    float* res  = (float*)d_out;
    float* wout = res + res_elems;
    const int write_w = (out_size >= 2 * res_elems) ? 1 : 0;

    sampler_kernel<<<n_rows, 256>>>(time_seq, dt_seq, ev_w, exp_raw, unif,
                                    emb, scale, bias, res, wout, write_w);
}

// round 5
// speedup vs baseline: 1.5780x; 1.0741x over previous
#include <cuda_runtime.h>
#include <math.h>
#include <stdint.h>

#define NSAMP  8
#define NEXP   256
#define NMARK  10
#define KBOUND 40
#define MAXROWS 65536

__device__ float g_upper[MAXROWS];

// cos with explicit Cody-Waite reduction by 2*pi (t up to ~350), then MUFU cos.
__device__ __forceinline__ float cos_cw(float t) {
    const float INV2PI   = 0.15915494309189535f;
    const float TWOPI_HI = 6.2831854820251465f;
    const float TWOPI_LO = -1.7484555e-07f;
    float k = rintf(t * INV2PI);
    float r = fmaf(-k, TWOPI_HI, t);
    r = fmaf(-k, TWOPI_LO, r);
    return __cosf(r);
}

// sum_m softplus(sc[m]*c + c0[m]) with a SINGLE log (10 EX2 + 1 LG2).
// NOTE: arithmetic kept bit-identical to the passing round-4 kernel.
__device__ __forceinline__ float total_intensity_reg(float c,
                                                     const float* __restrict__ c0,
                                                     const float* __restrict__ sc) {
    float lin = 0.0f, prod = 1.0f;
#pragma unroll
    for (int m = 0; m < NMARK; m++) {
        float x = fmaf(sc[m], c, c0[m]);
        lin += fmaxf(x, 0.0f);
        prod *= (1.0f + __expf(-fabsf(x)));
    }
    return lin + __logf(prod);
}

__device__ __forceinline__ void cp_async16(void* smem_dst, const void* gmem_src) {
    unsigned saddr = (unsigned)__cvta_generic_to_shared(smem_dst);
    asm volatile("cp.async.cg.shared.global [%0], [%1], 16;\n"
                 :: "r"(saddr), "l"(gmem_src) : "memory");
}

// detect int64 vs int32 encoding of event_seq (LE int64, values < 20 => odd
// words are all zero), then return event id for `row`. Full-warp collective.
__device__ __forceinline__ int load_event(const int* __restrict__ ev_w,
                                          int row, int lane) {
    int a = 0;
    if (lane < NMARK) a = ev_w[2 * lane + 1] | ev_w[2 * (lane + NMARK) + 1];
    unsigned ball = __ballot_sync(0xffffffffu, a != 0);
    return (ball == 0u) ? ev_w[2 * row] : ev_w[row];
}

// ---- kernel A: per-row intensity upper bound (one warp per row) ----
__global__ void __launch_bounds__(256) upper_kernel(
    const float* __restrict__ time_seq,
    const float* __restrict__ dt_seq,
    const int*   __restrict__ ev_w,
    const float* __restrict__ emb,
    const float* __restrict__ scale,
    const float* __restrict__ bias,
    int n_rows)
{
    const int lane = threadIdx.x & 31;
    const int warp = threadIdx.x >> 5;
    const int row  = blockIdx.x * 8 + warp;
    if (row >= n_rows) return;

    const int ev = load_event(ev_w, row, lane);

    float e = 0.0f, s = 0.0f;
    if (lane < NMARK) {
        e = emb[ev * NMARK + lane] + bias[lane];
        s = scale[lane];
    }
    float c0r[NMARK], scr[NMARK];
#pragma unroll
    for (int m = 0; m < NMARK; m++) {
        c0r[m] = __shfl_sync(0xffffffffu, e, m);
        scr[m] = __shfl_sync(0xffffffffu, s, m);
    }

    const float t0  = time_seq[row];
    const float dtv = dt_seq[row];

    // lanes 0..31 take k=lane; lanes 0..7 also take k=lane+32 (KBOUND=40)
    float lam;
    {
        float t = fmaf(dtv, (float)lane * (1.0f / 39.0f), t0);
        lam = total_intensity_reg(cos_cw(t), c0r, scr);
    }
    if (lane < KBOUND - 32) {
        float t = fmaf(dtv, (float)(lane + 32) * (1.0f / 39.0f), t0);
        lam = fmaxf(lam, total_intensity_reg(cos_cw(t), c0r, scr));
    }
#pragma unroll
    for (int o = 16; o; o >>= 1)
        lam = fmaxf(lam, __shfl_xor_sync(0xffffffffu, lam, o));
    if (lane == 0) g_upper[row] = 1.5f * lam;   // OVER_SAMPLE_RATE
}

// ---- kernel B: candidates + accept + min-reduce (one block per row) ----
__global__ void __launch_bounds__(256, 8) sampler_kernel(
    const float* __restrict__ time_seq,
    const int*   __restrict__ ev_w,
    const float* __restrict__ exp_raw,
    const float* __restrict__ unif,
    const float* __restrict__ emb,
    const float* __restrict__ scale,
    const float* __restrict__ bias,
    float* __restrict__ out_res,
    float* __restrict__ out_w,
    int write_w)
{
    const int row  = blockIdx.x;
    const int tid  = threadIdx.x;
    const int lane = tid & 31;
    const int warp = tid >> 5;

    __shared__ __align__(16) float s_unif[NSAMP * NEXP];  // 8 KB
    __shared__ __align__(16) float s_ex[NEXP];
    __shared__ __align__(16) float s_tot[NEXP];
    __shared__ float s_cs[8][2 * NMARK];   // per-warp {c0[10], sc[10]}

    // prefetch this block's unif slice (8 KB) via cp.async
    {
        const float* urow = unif + (size_t)row * (NSAMP * NEXP) + 8 * tid;
        cp_async16(&s_unif[8 * tid],     urow);
        cp_async16(&s_unif[8 * tid + 4], urow + 4);
        asm volatile("cp.async.commit_group;\n" ::: "memory");
    }

    const float exr   = exp_raw[(size_t)row * NEXP + tid];
    const float upper = g_upper[row];
    const float t0    = time_seq[row];

    // per-warp c0/sc fill: no block barrier needed (emb/scale hit L1)
    const int ev = load_event(ev_w, row, lane);
    if (lane < NMARK) {
        s_cs[warp][lane]         = emb[ev * NMARK + lane] + bias[lane];
        s_cs[warp][NMARK + lane] = scale[lane];
    }
    __syncwarp();

    // ---- phase 1: per-candidate ex + total intensity -> smem ----
    const float ex = __fdividef(exr, upper);
    const float c  = cos_cw(t0 + ex);
    float lin = 0.0f, prod = 1.0f;
#pragma unroll
    for (int m = 0; m < NMARK; m++) {
        float x = fmaf(s_cs[warp][NMARK + m], c, s_cs[warp][m]);
        lin += fmaxf(x, 0.0f);
        prod *= (1.0f + __expf(-fabsf(x)));
    }
    const float total = lin + __logf(prod);
    s_ex[tid]  = ex;
    s_tot[tid] = total;

    asm volatile("cp.async.wait_group 0;\n" ::: "memory");
    __syncthreads();   // the only block barrier

    // ---- phase 2: warp j owns sample slot j; LDS.128, conflict-free ----
    {
        const int j = warp;
        const float4* su = (const float4*)(s_unif + j * NEXP);
        const float4* pe = (const float4*)s_ex;
        const float4* pt = (const float4*)s_tot;
        float m = INFINITY;
#pragma unroll
        for (int half = 0; half < 2; half++) {
            int q = 32 * half + lane;
            float4 u4 = su[q];
            float4 e4 = pe[q];
            float4 t4 = pt[q];
            if (u4.x * upper < t4.x) m = fminf(m, e4.x);
            if (u4.y * upper < t4.y) m = fminf(m, e4.y);
            if (u4.z * upper < t4.z) m = fminf(m, e4.z);
            if (u4.w * upper < t4.w) m = fminf(m, e4.w);
        }
#pragma unroll
        for (int o = 16; o; o >>= 1)
            m = fminf(m, __shfl_xor_sync(0xffffffffu, m, o));
        if (lane == 0) {
            float r = isinf(m) ? 5.0f : m;     // DTIME_MAX when none accepted
            r = fminf(r, 1e5f);
            out_res[row * NSAMP + j] = r;
            if (write_w) out_w[row * NSAMP + j] = 0.125f;
        }
    }
}

extern "C" void kernel_launch(void* const* d_in, const int* in_sizes, int n_in,
                              void* d_out, int out_size) {
    const float* time_seq = (const float*)d_in[0];
    const float* dt_seq   = (const float*)d_in[1];
    const int*   ev_w     = (const int*)  d_in[2];
    const float* exp_raw  = (const float*)d_in[3];
    const float* unif     = (const float*)d_in[4];
    const float* emb      = (const float*)d_in[5];
    const float* scale    = (const float*)d_in[6];
    const float* bias     = (const float*)d_in[7];

    const int n_rows    = in_sizes[0];          // B*S = 16384
    const int res_elems = n_rows * NSAMP;
    float* res  = (float*)d_out;
    float* wout = res + res_elems;
    const int write_w = (out_size >= 2 * res_elems) ? 1 : 0;

    upper_kernel<<<(n_rows + 7) / 8, 256>>>(time_seq, dt_seq, ev_w,
                                            emb, scale, bias, n_rows);
    sampler_kernel<<<n_rows, 256>>>(time_seq, ev_w, exp_raw, unif,
                                    emb, scale, bias, res, wout, write_w);
}